// round 14
// baseline (speedup 1.0000x reference)
#include <cuda_runtime.h>
#include <cuda_fp16.h>

#define NH 256
#define NW 256
#define GH2 512
#define GW2 512
#define NA 5
#define NC 12
#define FREQ (GH2*GW2)   // 262144

#define SZ_X   (NA*NH*NW)      // 327680
#define SZ_MPS (NC*NH*NW)      // 786432
#define SZ_K   (NA*NA*FREQ)    // 6553600

// Skewed smem index: conflict-free for the radix-8 pass patterns.
#define IDX(i) ((i) + ((i) >> 5) + 8*((i) >> 6))
#define SMEM_N 588             // stride ≡ 12 (mod 32): conflict-free slot offsets

// Layouts:
//  g_fullh: [c][b or a][w(512)][h(512)] half2  (h contiguous)
//  g_mid  : [c][b][col(512)][row(256)] float2  (p01 -> p2)
//  g_mid2h: [c][a][row(256)][col(512)] half2   (p4 -> p5)
//  g_KTh  : [q=a*5+b][w][h] half2 (UNscaled; SCALE applied in p3 store)
__device__ __half2 g_fullh[NC*NA*FREQ];    // 62.9 MB
__device__ float2  g_mid  [NC*NA*NH*GW2];  // 62.9 MB
__device__ __half2 g_mid2h[NC*NA*NH*GW2];  // 31.5 MB
__device__ __half2 g_KTh  [NA*NA*FREQ];    // 26.2 MB

__device__ __forceinline__ float2 cadd(float2 a, float2 b) { return make_float2(a.x+b.x, a.y+b.y); }
__device__ __forceinline__ float2 csub(float2 a, float2 b) { return make_float2(a.x-b.x, a.y-b.y); }
__device__ __forceinline__ float2 cmul(float2 a, float2 b) {
    return make_float2(a.x*b.x - a.y*b.y, a.x*b.y + a.y*b.x);
}

__device__ __forceinline__ void build_tw(float2* tw, int t) {
    #pragma unroll
    for (int u = 0; u < 2; u++) {
        int j = t + 256*u;
        float sv, cv;
        sincosf(-6.283185307179586f * (float)j * (1.0f/512.0f), &sv, &cv);
        tw[j] = make_float2(cv, sv);
    }
}

// In-register DFT-8 (DIF), natural-order outputs.
template<bool INV>
__device__ __forceinline__ void dft8(float2* x) {
    const float H = 0.70710678118654752f;
    float2 t0 = cadd(x[0], x[4]), t4 = csub(x[0], x[4]);
    float2 t1 = cadd(x[1], x[5]), t5 = csub(x[1], x[5]);
    float2 t2 = cadd(x[2], x[6]), t6 = csub(x[2], x[6]);
    float2 t3 = cadd(x[3], x[7]), t7 = csub(x[3], x[7]);
    if (!INV) {
        t5 = make_float2(H*(t5.x + t5.y), H*(t5.y - t5.x));
        t6 = make_float2(t6.y, -t6.x);
        t7 = make_float2(H*(t7.y - t7.x), -H*(t7.x + t7.y));
    } else {
        t5 = make_float2(H*(t5.x - t5.y), H*(t5.x + t5.y));
        t6 = make_float2(-t6.y, t6.x);
        t7 = make_float2(-H*(t7.x + t7.y), H*(t7.x - t7.y));
    }
    float2 u0 = cadd(t0, t2), u2 = csub(t0, t2);
    float2 u1 = cadd(t1, t3), u3 = csub(t1, t3);
    u3 = INV ? make_float2(-u3.y, u3.x) : make_float2(u3.y, -u3.x);
    float2 v0 = cadd(t4, t6), v2 = csub(t4, t6);
    float2 v1 = cadd(t5, t7), v3 = csub(t5, t7);
    v3 = INV ? make_float2(-v3.y, v3.x) : make_float2(v3.y, -v3.x);
    x[0] = cadd(u0, u1); x[4] = csub(u0, u1);
    x[2] = cadd(u2, u3); x[6] = csub(u2, u3);
    x[1] = cadd(v0, v1); x[5] = csub(v0, v1);
    x[3] = cadd(v2, v3); x[7] = csub(v2, v3);
}

// 512-pt radix-8 Stockham with register IO.
// In:  x[j] = point (tl + 64j).  Out: x[r] = frequency (tl + 64r).
// Caller must sync before call (pass 0 writes smem). No trailing sync.
template<bool INV>
__device__ __forceinline__ void fft512_reg(float2* x, float* re, float* im,
                                           const float2* tw, int tl) {
    dft8<INV>(x);
    #pragma unroll
    for (int r = 0; r < 8; r++) {
        float2 v = x[r];
        if (r > 0) {
            float2 w = tw[tl*r];
            float wy = INV ? -w.y : w.y;
            v = make_float2(x[r].x*w.x - x[r].y*wy, x[r].x*wy + x[r].y*w.x);
        }
        int o = 8*tl + r;
        re[IDX(o)] = v.x; im[IDX(o)] = v.y;
    }
    __syncthreads();
    #pragma unroll
    for (int j = 0; j < 8; j++) {
        int i = tl + 64*j;
        x[j] = make_float2(re[IDX(i)], im[IDX(i)]);
    }
    __syncthreads();
    dft8<INV>(x);
    {
        int q = tl & 7, p = tl >> 3;
        int ob = q + 64*p;
        #pragma unroll
        for (int r = 0; r < 8; r++) {
            float2 v = x[r];
            if (r > 0) {
                float2 w = tw[(p*r) << 3];
                float wy = INV ? -w.y : w.y;
                v = make_float2(x[r].x*w.x - x[r].y*wy, x[r].x*wy + x[r].y*w.x);
            }
            int o = ob + 8*r;
            re[IDX(o)] = v.x; im[IDX(o)] = v.y;
        }
    }
    __syncthreads();
    #pragma unroll
    for (int j = 0; j < 8; j++) {
        int i = tl + 64*j;
        x[j] = make_float2(re[IDX(i)], im[IDX(i)]);
    }
    dft8<INV>(x);
}

__global__ void zero_out(float* __restrict__ o, int n) {
    int i = blockIdx.x*256 + threadIdx.x;
    if (i < n) o[i] = 0.f;
}

// -------- P01: grid-fused K-transpose (z<25) + row-FFT (z>=25) --------------
// Transpose tile buffers alias the FFT scratch (branch-disjoint usage).
__global__ void __launch_bounds__(256, 7)
p01_ktrans_rowfft(const float* __restrict__ kr, const float* __restrict__ ki,
                  const float* __restrict__ xr, const float* __restrict__ xi,
                  const float* __restrict__ mr, const float* __restrict__ mi) {
    __shared__ float sre[4][SMEM_N], sim[4][SMEM_N];
    __shared__ float2 tw[512];
    int t = threadIdx.x;
    int z = blockIdx.z;
    if (z < NA*NA) {
        // ---- K transpose tile (uses scratch as [32][33] tiles) ----
        float (*tre)[33] = (float(*)[33])&sre[0][0];   // 1056 floats <= 2352
        float (*tim)[33] = (float(*)[33])&sim[0][0];
        int q = z;
        int w0 = blockIdx.x*32, h0 = blockIdx.y*32;
        int tx = t & 31, ty = t >> 5;
        size_t base = (size_t)q*FREQ;
        #pragma unroll
        for (int dy = 0; dy < 4; dy++) {
            int h = h0 + ty + 8*dy;
            size_t o = base + (size_t)h*GW2 + w0 + tx;
            tre[ty + 8*dy][tx] = kr[o];
            tim[ty + 8*dy][tx] = ki[o];
        }
        __syncthreads();
        #pragma unroll
        for (int dy = 0; dy < 4; dy++) {
            int w = w0 + ty + 8*dy;
            g_KTh[base + (size_t)w*GH2 + h0 + tx] =
                __floats2half2_rn(tre[tx][ty + 8*dy], tim[tx][ty + 8*dy]);
        }
        return;
    }
    // ---- row-FFT block ----
    build_tw(tw, t);
    int id = (z - NA*NA)*256 + blockIdx.y*16 + blockIdx.x;   // [0, 3840)
    int c  = id % NC;
    int rem = id / NC;
    int b  = rem % NA;
    int rt = rem / NA;                   // row tile [0,64)
    int f = t >> 6, tl = t & 63;
    int row = rt*4 + f;
    float2 x[8];
    #pragma unroll
    for (int j = 0; j < 8; j++) {
        int i = tl + 64*j;
        float2 v = make_float2(0.f, 0.f);
        if (j >= 2 && j < 6) {
            int col = i - 128;
            int xo = (b*NH + row)*NW + col;
            int mo = (c*NH + row)*NW + col;
            v = cmul(make_float2(xr[xo], xi[xo]), make_float2(mr[mo], mi[mo]));
        }
        x[j] = v;
    }
    __syncthreads();                       // tw table ready
    fft512_reg<false>(x, sre[f], sim[f], tw, tl);
    __syncthreads();
    #pragma unroll
    for (int r = 0; r < 8; r++) {
        int o = tl + 64*r;
        sre[f][IDX(o)] = x[r].x; sim[f][IDX(o)] = x[r].y;
    }
    __syncthreads();
    int f2 = t & 3, tl2 = t >> 2;
    float2* dst = g_mid + (size_t)(c*NA + b)*GW2*NH;   // [col][row]
    int rowbase = rt*4 + f2;
    #pragma unroll
    for (int j = 0; j < 8; j++) {
        int i = tl2 + 64*j;                // col
        dst[(size_t)i*NH + rowbase] = make_float2(sre[f2][IDX(i)], sim[f2][IDX(i)]);
    }
}

// -------- P2: 4 cols/block: col-FFT, direct reg IO (g_mid -> g_fullh) -------
__global__ void __launch_bounds__(256, 7)
p2_colfft() {
    __shared__ float sre[4][SMEM_N], sim[4][SMEM_N];
    __shared__ float2 tw[512];
    int t = threadIdx.x;
    build_tw(tw, t);
    int f = t >> 6, tl = t & 63;
    int w = blockIdx.x*4 + f, b = blockIdx.y, c = blockIdx.z;
    const float2* src = g_mid + ((size_t)(c*NA + b)*GW2 + w)*NH;  // [col][row]
    float2 x[8];
    #pragma unroll
    for (int j = 0; j < 8; j++) {
        int i = tl + 64*j;
        x[j] = (j >= 2 && j < 6) ? src[i - 128] : make_float2(0.f, 0.f);
    }
    __syncthreads();
    fft512_reg<false>(x, sre[f], sim[f], tw, tl);
    __half2* dst = g_fullh + ((size_t)(c*NA + b)*GW2 + w)*GH2;    // [w][h]
    #pragma unroll
    for (int r = 0; r < 8; r++)
        dst[tl + 64*r] = __floats2half2_rn(x[r].x, x[r].y);
}

// -------- P3: per-frequency [A,A] contraction, all-half2 streams ------------
__global__ void __launch_bounds__(256, 4)
p3_contract() {
    int idx = blockIdx.x*256 + threadIdx.x;
    const float SCALE = 1.0f / 65536.0f;     // OS^2 / (512*512) ortho norms
    __half2 K[NA*NA];
    #pragma unroll
    for (int q = 0; q < NA*NA; q++)
        K[q] = g_KTh[(size_t)q*FREQ + idx];
    float2 fx[NA];
    #pragma unroll
    for (int b = 0; b < NA; b++)
        fx[b] = __half22float2(g_fullh[(size_t)b*FREQ + idx]);
    for (int c = 0; c < NC; c++) {
        float2 fxn[NA];
        if (c + 1 < NC) {
            #pragma unroll
            for (int b = 0; b < NA; b++)
                fxn[b] = __half22float2(g_fullh[(size_t)((c+1)*NA + b)*FREQ + idx]);
        }
        #pragma unroll
        for (int a = 0; a < NA; a++) {
            float2 acc = make_float2(0.f, 0.f);
            #pragma unroll
            for (int b = 0; b < NA; b++) {
                float2 kv = __half22float2(K[a*NA + b]);
                float2 f  = fx[b];
                acc.x += f.x*kv.x - f.y*kv.y;
                acc.y += f.x*kv.y + f.y*kv.x;
            }
            g_fullh[(size_t)(c*NA + a)*FREQ + idx] =
                __floats2half2_rn(acc.x*SCALE, acc.y*SCALE);
        }
        if (c + 1 < NC) {
            #pragma unroll
            for (int b = 0; b < NA; b++)
                fx[b] = fxn[b];
        }
    }
}

// -------- P4: 8 w/block (512 thr): col-IFFT, crop rows, half2 out -----------
__global__ void __launch_bounds__(512, 4)
p4_colifft() {
    __shared__ float sre[8][SMEM_N], sim[8][SMEM_N];
    __shared__ float2 tw[512];
    int t = threadIdx.x;
    if (t < 256) build_tw(tw, t);
    int f = t >> 6, tl = t & 63;
    int w = blockIdx.x*8 + f, a = blockIdx.y, c = blockIdx.z;
    const __half2* src = g_fullh + ((size_t)(c*NA + a)*GW2 + w)*GH2;  // [w][h]
    float2 x[8];
    #pragma unroll
    for (int j = 0; j < 8; j++)
        x[j] = __half22float2(src[tl + 64*j]);
    __syncthreads();                       // tw ready, smem free
    fft512_reg<true>(x, sre[f], sim[f], tw, tl);
    __syncthreads();
    #pragma unroll
    for (int r = 2; r < 6; r++) {          // keep rows 128..383
        int o = tl + 64*r;
        sre[f][IDX(o)] = x[r].x; sim[f][IDX(o)] = x[r].y;
    }
    __syncthreads();
    int f2 = t & 7, tl2 = t >> 3;
    __half2* dst = g_mid2h + (size_t)(c*NA + a)*NH*GW2;   // [row][col]
    int wb = blockIdx.x*8 + f2;
    #pragma unroll
    for (int j = 2; j < 6; j++) {
        int i = tl2 + 64*j;                // h
        dst[(size_t)(i - 128)*GW2 + wb] =
            __floats2half2_rn(sre[f2][IDX(i)], sim[f2][IDX(i)]);
    }
}

// -------- P5: 4 coils x3 iters: row-IFFT, crop, conj(mps), sum_c ------------
// Grid: (a fastest, row) so the 5 a-blocks of one row share mps in L2.
__global__ void __launch_bounds__(256, 7)
p5_combine(const float* __restrict__ mr, const float* __restrict__ mi,
           float* __restrict__ out, int out_cap) {
    __shared__ float sre[4][SMEM_N], sim[4][SMEM_N];
    __shared__ float2 tw[512];
    __shared__ float2 sacc[4][256];
    int t = threadIdx.x;
    build_tw(tw, t);
    int f = t >> 6, tl = t & 63;
    int a = blockIdx.x, r = blockIdx.y;
    float2 acc[4] = {{0,0},{0,0},{0,0},{0,0}};
    for (int it = 0; it < 3; it++) {
        int c = it*4 + f;
        const __half2* src = g_mid2h + ((size_t)(c*NA + a)*NH + r)*GW2;  // [row][col]
        float2 x[8];
        #pragma unroll
        for (int j = 0; j < 8; j++)
            x[j] = __half22float2(src[tl + 64*j]);
        __syncthreads();               // smem (tw at it=0; prior pass reads after)
        fft512_reg<true>(x, sre[f], sim[f], tw, tl);
        #pragma unroll
        for (int rr = 2; rr < 6; rr++) {
            int col = tl + 64*rr - 128;
            int mo = (c*NH + r)*NW + col;
            float2 m = make_float2(mr[mo], -mi[mo]);
            acc[rr-2] = cadd(acc[rr-2], cmul(x[rr], m));
        }
    }
    #pragma unroll
    for (int jj = 0; jj < 4; jj++)
        sacc[f][tl + 64*jj] = acc[jj];
    __syncthreads();
    int col = t;
    float2 s = cadd(cadd(sacc[0][col], sacc[1][col]),
                    cadd(sacc[2][col], sacc[3][col]));
    int i = (a*NH + r)*NW + col;
    if (i        < out_cap) out[i]        = s.x;   // real plane
    if (i + SZ_X < out_cap) out[i + SZ_X] = s.y;   // imag plane
}

extern "C" void kernel_launch(void* const* d_in, const int* in_sizes, int n_in,
                              void* d_out, int out_size) {
    // ---- strict binding by verified size fingerprint (validated in R5) ----
    const float *ptr_by_sz[3][2] = {{0,0},{0,0},{0,0}};
    int idx_by_sz[3][2] = {{-1,-1},{-1,-1},{-1,-1}};
    bool ok = (n_in == 6);
    if (ok) {
        for (int i = 0; i < 6; i++) {
            long long s = in_sizes[i];
            int which = -1;
            if (s == SZ_X   || s == (long long)SZ_X*4)   which = 0;
            else if (s == SZ_MPS || s == (long long)SZ_MPS*4) which = 1;
            else if (s == SZ_K   || s == (long long)SZ_K*4)   which = 2;
            if (which < 0) { ok = false; break; }
            if      (idx_by_sz[which][0] < 0) { idx_by_sz[which][0] = i; ptr_by_sz[which][0] = (const float*)d_in[i]; }
            else if (idx_by_sz[which][1] < 0) { idx_by_sz[which][1] = i; ptr_by_sz[which][1] = (const float*)d_in[i]; }
            else { ok = false; break; }
        }
        if (ok)
            for (int w = 0; w < 3; w++)
                if (idx_by_sz[w][1] < 0) ok = false;
    }
    if (!ok) {
        int n = out_size > 0 ? out_size : 1;
        zero_out<<<(n + 255)/256, 256>>>((float*)d_out, n);
        return;
    }
    bool real_first = (idx_by_sz[0][0] < idx_by_sz[2][0]);
    const float* xr = ptr_by_sz[0][real_first ? 0 : 1];
    const float* xi = ptr_by_sz[0][real_first ? 1 : 0];
    const float* mr = ptr_by_sz[1][real_first ? 0 : 1];
    const float* mi = ptr_by_sz[1][real_first ? 1 : 0];
    const float* kr = ptr_by_sz[2][real_first ? 0 : 1];
    const float* ki = ptr_by_sz[2][real_first ? 1 : 0];

    // z: [0,25) = K-transpose tiles; [25,40) = 3840 row-FFT blocks (15*256).
    p01_ktrans_rowfft<<<dim3(16, 16, NA*NA + 15), 256>>>(kr, ki, xr, xi, mr, mi);
    p2_colfft <<<dim3(GW2/4, NA, NC), 256>>>();
    p3_contract<<<FREQ/256, 256>>>();
    p4_colifft<<<dim3(GW2/8, NA, NC), 512>>>();
    p5_combine<<<dim3(NA, NH), 256>>>(mr, mi, (float*)d_out, out_size);
}

// round 15
// speedup vs baseline: 1.1286x; 1.1286x over previous
#include <cuda_runtime.h>
#include <cuda_fp16.h>

#define NH 256
#define NW 256
#define GH2 512
#define GW2 512
#define NA 5
#define NC 12
#define FREQ (GH2*GW2)   // 262144

#define SZ_X   (NA*NH*NW)      // 327680
#define SZ_MPS (NC*NH*NW)      // 786432
#define SZ_K   (NA*NA*FREQ)    // 6553600

// Skewed smem index: conflict-free for the radix-8 pass patterns.
#define IDX(i) ((i) + ((i) >> 5) + 8*((i) >> 6))
#define SMEM_N 588             // stride ≡ 12 (mod 32): conflict-free slot offsets

// Layouts:
//  g_fullh: [c][b or a][w(512)][h(512)] half2  (h contiguous)
//  g_mid  : [c][b][col(512)][row(256)] float2  (p01 -> p2)
//  g_mid2h: [c][a][row(256)][col(512)] half2   (p4 -> p5)
//  g_KTh  : [q=a*5+b][w][h] half2 (UNscaled; SCALE applied in p3 store)
__device__ __half2 g_fullh[NC*NA*FREQ];    // 62.9 MB
__device__ float2  g_mid  [NC*NA*NH*GW2];  // 62.9 MB
__device__ __half2 g_mid2h[NC*NA*NH*GW2];  // 31.5 MB
__device__ __half2 g_KTh  [NA*NA*FREQ];    // 26.2 MB

__device__ __forceinline__ float2 cadd(float2 a, float2 b) { return make_float2(a.x+b.x, a.y+b.y); }
__device__ __forceinline__ float2 csub(float2 a, float2 b) { return make_float2(a.x-b.x, a.y-b.y); }
__device__ __forceinline__ float2 cmul(float2 a, float2 b) {
    return make_float2(a.x*b.x - a.y*b.y, a.x*b.y + a.y*b.x);
}

// Named barrier over a 64-thread (2-warp) FFT group. Group f uses id f+1;
// id 0 stays reserved for block-wide __syncthreads.
__device__ __forceinline__ void bar64(int id) {
    asm volatile("bar.sync %0, 64;" :: "r"(id) : "memory");
}

__device__ __forceinline__ void build_tw(float2* tw, int t) {
    #pragma unroll
    for (int u = 0; u < 2; u++) {
        int j = t + 256*u;
        float sv, cv;
        sincosf(-6.283185307179586f * (float)j * (1.0f/512.0f), &sv, &cv);
        tw[j] = make_float2(cv, sv);
    }
}

// In-register DFT-8 (DIF), natural-order outputs.
template<bool INV>
__device__ __forceinline__ void dft8(float2* x) {
    const float H = 0.70710678118654752f;
    float2 t0 = cadd(x[0], x[4]), t4 = csub(x[0], x[4]);
    float2 t1 = cadd(x[1], x[5]), t5 = csub(x[1], x[5]);
    float2 t2 = cadd(x[2], x[6]), t6 = csub(x[2], x[6]);
    float2 t3 = cadd(x[3], x[7]), t7 = csub(x[3], x[7]);
    if (!INV) {
        t5 = make_float2(H*(t5.x + t5.y), H*(t5.y - t5.x));
        t6 = make_float2(t6.y, -t6.x);
        t7 = make_float2(H*(t7.y - t7.x), -H*(t7.x + t7.y));
    } else {
        t5 = make_float2(H*(t5.x - t5.y), H*(t5.x + t5.y));
        t6 = make_float2(-t6.y, t6.x);
        t7 = make_float2(-H*(t7.x + t7.y), H*(t7.x - t7.y));
    }
    float2 u0 = cadd(t0, t2), u2 = csub(t0, t2);
    float2 u1 = cadd(t1, t3), u3 = csub(t1, t3);
    u3 = INV ? make_float2(-u3.y, u3.x) : make_float2(u3.y, -u3.x);
    float2 v0 = cadd(t4, t6), v2 = csub(t4, t6);
    float2 v1 = cadd(t5, t7), v3 = csub(t5, t7);
    v3 = INV ? make_float2(-v3.y, v3.x) : make_float2(v3.y, -v3.x);
    x[0] = cadd(u0, u1); x[4] = csub(u0, u1);
    x[2] = cadd(u2, u3); x[6] = csub(u2, u3);
    x[1] = cadd(v0, v1); x[5] = csub(v0, v1);
    x[3] = cadd(v2, v3); x[7] = csub(v2, v3);
}

// 512-pt radix-8 Stockham with register IO; group-scoped named barriers.
// In:  x[j] = point (tl + 64j).  Out: x[r] = frequency (tl + 64r).
// Caller must group-sync before call if the slot is being reused. No trailing sync.
template<bool INV>
__device__ __forceinline__ void fft512_reg(float2* x, float* re, float* im,
                                           const float2* tw, int tl, int bid) {
    dft8<INV>(x);
    #pragma unroll
    for (int r = 0; r < 8; r++) {
        float2 v = x[r];
        if (r > 0) {
            float2 w = tw[tl*r];
            float wy = INV ? -w.y : w.y;
            v = make_float2(x[r].x*w.x - x[r].y*wy, x[r].x*wy + x[r].y*w.x);
        }
        int o = 8*tl + r;
        re[IDX(o)] = v.x; im[IDX(o)] = v.y;
    }
    bar64(bid);
    #pragma unroll
    for (int j = 0; j < 8; j++) {
        int i = tl + 64*j;
        x[j] = make_float2(re[IDX(i)], im[IDX(i)]);
    }
    bar64(bid);
    dft8<INV>(x);
    {
        int q = tl & 7, p = tl >> 3;
        int ob = q + 64*p;
        #pragma unroll
        for (int r = 0; r < 8; r++) {
            float2 v = x[r];
            if (r > 0) {
                float2 w = tw[(p*r) << 3];
                float wy = INV ? -w.y : w.y;
                v = make_float2(x[r].x*w.x - x[r].y*wy, x[r].x*wy + x[r].y*w.x);
            }
            int o = ob + 8*r;
            re[IDX(o)] = v.x; im[IDX(o)] = v.y;
        }
    }
    bar64(bid);
    #pragma unroll
    for (int j = 0; j < 8; j++) {
        int i = tl + 64*j;
        x[j] = make_float2(re[IDX(i)], im[IDX(i)]);
    }
    dft8<INV>(x);
}

__global__ void zero_out(float* __restrict__ o, int n) {
    int i = blockIdx.x*256 + threadIdx.x;
    if (i < n) o[i] = 0.f;
}

// -------- P01: grid-fused K-transpose (z<25) + row-FFT (z>=25) --------------
__global__ void __launch_bounds__(256)
p01_ktrans_rowfft(const float* __restrict__ kr, const float* __restrict__ ki,
                  const float* __restrict__ xr, const float* __restrict__ xi,
                  const float* __restrict__ mr, const float* __restrict__ mi) {
    __shared__ float tre[32][33], tim[32][33];
    __shared__ float sre[4][SMEM_N], sim[4][SMEM_N];
    __shared__ float2 tw[512];
    int t = threadIdx.x;
    int z = blockIdx.z;
    if (z < NA*NA) {
        // ---- K transpose tile ----
        int q = z;
        int w0 = blockIdx.x*32, h0 = blockIdx.y*32;
        int tx = t & 31, ty = t >> 5;
        size_t base = (size_t)q*FREQ;
        #pragma unroll
        for (int dy = 0; dy < 4; dy++) {
            int h = h0 + ty + 8*dy;
            size_t o = base + (size_t)h*GW2 + w0 + tx;
            tre[ty + 8*dy][tx] = kr[o];
            tim[ty + 8*dy][tx] = ki[o];
        }
        __syncthreads();
        #pragma unroll
        for (int dy = 0; dy < 4; dy++) {
            int w = w0 + ty + 8*dy;
            g_KTh[base + (size_t)w*GH2 + h0 + tx] =
                __floats2half2_rn(tre[tx][ty + 8*dy], tim[tx][ty + 8*dy]);
        }
        return;
    }
    // ---- row-FFT block ----
    build_tw(tw, t);
    int id = (z - NA*NA)*256 + blockIdx.y*16 + blockIdx.x;   // [0, 3840)
    int c  = id % NC;
    int rem = id / NC;
    int b  = rem % NA;
    int rt = rem / NA;                   // row tile [0,64)
    int f = t >> 6, tl = t & 63;
    int row = rt*4 + f;
    float2 x[8];
    #pragma unroll
    for (int j = 0; j < 8; j++) {
        int i = tl + 64*j;
        float2 v = make_float2(0.f, 0.f);
        if (j >= 2 && j < 6) {
            int col = i - 128;
            int xo = (b*NH + row)*NW + col;
            int mo = (c*NH + row)*NW + col;
            v = cmul(make_float2(xr[xo], xi[xo]), make_float2(mr[mo], mi[mo]));
        }
        x[j] = v;
    }
    __syncthreads();                       // tw table ready (block-wide)
    fft512_reg<false>(x, sre[f], sim[f], tw, tl, f + 1);
    bar64(f + 1);                          // group slot reads done
    #pragma unroll
    for (int r = 0; r < 8; r++) {
        int o = tl + 64*r;
        sre[f][IDX(o)] = x[r].x; sim[f][IDX(o)] = x[r].y;
    }
    __syncthreads();                       // cross-group staging read below
    int f2 = t & 3, tl2 = t >> 2;
    float2* dst = g_mid + (size_t)(c*NA + b)*GW2*NH;   // [col][row]
    int rowbase = rt*4 + f2;
    #pragma unroll
    for (int j = 0; j < 8; j++) {
        int i = tl2 + 64*j;                // col
        dst[(size_t)i*NH + rowbase] = make_float2(sre[f2][IDX(i)], sim[f2][IDX(i)]);
    }
}

// -------- P2: 4 cols/block: col-FFT, direct reg IO (g_mid -> g_fullh) -------
__global__ void __launch_bounds__(256)
p2_colfft() {
    __shared__ float sre[4][SMEM_N], sim[4][SMEM_N];
    __shared__ float2 tw[512];
    int t = threadIdx.x;
    build_tw(tw, t);
    int f = t >> 6, tl = t & 63;
    int w = blockIdx.x*4 + f, b = blockIdx.y, c = blockIdx.z;
    const float2* src = g_mid + ((size_t)(c*NA + b)*GW2 + w)*NH;  // [col][row]
    float2 x[8];
    #pragma unroll
    for (int j = 0; j < 8; j++) {
        int i = tl + 64*j;
        x[j] = (j >= 2 && j < 6) ? src[i - 128] : make_float2(0.f, 0.f);
    }
    __syncthreads();                       // tw table ready (block-wide)
    fft512_reg<false>(x, sre[f], sim[f], tw, tl, f + 1);
    __half2* dst = g_fullh + ((size_t)(c*NA + b)*GW2 + w)*GH2;    // [w][h]
    #pragma unroll
    for (int r = 0; r < 8; r++)
        dst[tl + 64*r] = __floats2half2_rn(x[r].x, x[r].y);
}

// -------- P3: per-frequency [A,A] contraction, all-half2 streams ------------
__global__ void __launch_bounds__(256, 4)
p3_contract() {
    int idx = blockIdx.x*256 + threadIdx.x;
    const float SCALE = 1.0f / 65536.0f;     // OS^2 / (512*512) ortho norms
    __half2 K[NA*NA];
    #pragma unroll
    for (int q = 0; q < NA*NA; q++)
        K[q] = g_KTh[(size_t)q*FREQ + idx];
    float2 fx[NA];
    #pragma unroll
    for (int b = 0; b < NA; b++)
        fx[b] = __half22float2(g_fullh[(size_t)b*FREQ + idx]);
    for (int c = 0; c < NC; c++) {
        float2 fxn[NA];
        if (c + 1 < NC) {
            #pragma unroll
            for (int b = 0; b < NA; b++)
                fxn[b] = __half22float2(g_fullh[(size_t)((c+1)*NA + b)*FREQ + idx]);
        }
        #pragma unroll
        for (int a = 0; a < NA; a++) {
            float2 acc = make_float2(0.f, 0.f);
            #pragma unroll
            for (int b = 0; b < NA; b++) {
                float2 kv = __half22float2(K[a*NA + b]);
                float2 f  = fx[b];
                acc.x += f.x*kv.x - f.y*kv.y;
                acc.y += f.x*kv.y + f.y*kv.x;
            }
            g_fullh[(size_t)(c*NA + a)*FREQ + idx] =
                __floats2half2_rn(acc.x*SCALE, acc.y*SCALE);
        }
        if (c + 1 < NC) {
            #pragma unroll
            for (int b = 0; b < NA; b++)
                fx[b] = fxn[b];
        }
    }
}

// -------- P4: 8 w/block (512 thr): col-IFFT, crop rows, half2 out -----------
__global__ void __launch_bounds__(512)
p4_colifft() {
    __shared__ float sre[8][SMEM_N], sim[8][SMEM_N];
    __shared__ float2 tw[512];
    int t = threadIdx.x;
    if (t < 256) build_tw(tw, t);
    int f = t >> 6, tl = t & 63;
    int w = blockIdx.x*8 + f, a = blockIdx.y, c = blockIdx.z;
    const __half2* src = g_fullh + ((size_t)(c*NA + a)*GW2 + w)*GH2;  // [w][h]
    float2 x[8];
    #pragma unroll
    for (int j = 0; j < 8; j++)
        x[j] = __half22float2(src[tl + 64*j]);
    __syncthreads();                       // tw table ready (block-wide)
    fft512_reg<true>(x, sre[f], sim[f], tw, tl, f + 1);
    bar64(f + 1);                          // group slot reads done
    #pragma unroll
    for (int r = 2; r < 6; r++) {          // keep rows 128..383
        int o = tl + 64*r;
        sre[f][IDX(o)] = x[r].x; sim[f][IDX(o)] = x[r].y;
    }
    __syncthreads();                       // cross-group staging read below
    int f2 = t & 7, tl2 = t >> 3;
    __half2* dst = g_mid2h + (size_t)(c*NA + a)*NH*GW2;   // [row][col]
    int wb = blockIdx.x*8 + f2;
    #pragma unroll
    for (int j = 2; j < 6; j++) {
        int i = tl2 + 64*j;                // h
        dst[(size_t)(i - 128)*GW2 + wb] =
            __floats2half2_rn(sre[f2][IDX(i)], sim[f2][IDX(i)]);
    }
}

// -------- P5: 4 coils x3 iters: row-IFFT, crop, conj(mps), sum_c ------------
// Grid: (a fastest, row) so the 5 a-blocks of one row share mps in L2.
__global__ void __launch_bounds__(256)
p5_combine(const float* __restrict__ mr, const float* __restrict__ mi,
           float* __restrict__ out, int out_cap) {
    __shared__ float sre[4][SMEM_N], sim[4][SMEM_N];
    __shared__ float2 tw[512];
    __shared__ float2 sacc[4][256];
    int t = threadIdx.x;
    build_tw(tw, t);
    int f = t >> 6, tl = t & 63;
    int a = blockIdx.x, r = blockIdx.y;
    float2 acc[4] = {{0,0},{0,0},{0,0},{0,0}};
    __syncthreads();                       // tw table ready (block-wide)
    for (int it = 0; it < 3; it++) {
        int c = it*4 + f;
        const __half2* src = g_mid2h + ((size_t)(c*NA + a)*NH + r)*GW2;  // [row][col]
        float2 x[8];
        #pragma unroll
        for (int j = 0; j < 8; j++)
            x[j] = __half22float2(src[tl + 64*j]);
        bar64(f + 1);                  // group slot reads from prior iter done
        fft512_reg<true>(x, sre[f], sim[f], tw, tl, f + 1);
        #pragma unroll
        for (int rr = 2; rr < 6; rr++) {
            int col = tl + 64*rr - 128;
            int mo = (c*NH + r)*NW + col;
            float2 m = make_float2(mr[mo], -mi[mo]);
            acc[rr-2] = cadd(acc[rr-2], cmul(x[rr], m));
        }
    }
    #pragma unroll
    for (int jj = 0; jj < 4; jj++)
        sacc[f][tl + 64*jj] = acc[jj];
    __syncthreads();                       // cross-group reduction below
    int col = t;
    float2 s = cadd(cadd(sacc[0][col], sacc[1][col]),
                    cadd(sacc[2][col], sacc[3][col]));
    int i = (a*NH + r)*NW + col;
    if (i        < out_cap) out[i]        = s.x;   // real plane
    if (i + SZ_X < out_cap) out[i + SZ_X] = s.y;   // imag plane
}

extern "C" void kernel_launch(void* const* d_in, const int* in_sizes, int n_in,
                              void* d_out, int out_size) {
    // ---- strict binding by verified size fingerprint (validated in R5) ----
    const float *ptr_by_sz[3][2] = {{0,0},{0,0},{0,0}};
    int idx_by_sz[3][2] = {{-1,-1},{-1,-1},{-1,-1}};
    bool ok = (n_in == 6);
    if (ok) {
        for (int i = 0; i < 6; i++) {
            long long s = in_sizes[i];
            int which = -1;
            if (s == SZ_X   || s == (long long)SZ_X*4)   which = 0;
            else if (s == SZ_MPS || s == (long long)SZ_MPS*4) which = 1;
            else if (s == SZ_K   || s == (long long)SZ_K*4)   which = 2;
            if (which < 0) { ok = false; break; }
            if      (idx_by_sz[which][0] < 0) { idx_by_sz[which][0] = i; ptr_by_sz[which][0] = (const float*)d_in[i]; }
            else if (idx_by_sz[which][1] < 0) { idx_by_sz[which][1] = i; ptr_by_sz[which][1] = (const float*)d_in[i]; }
            else { ok = false; break; }
        }
        if (ok)
            for (int w = 0; w < 3; w++)
                if (idx_by_sz[w][1] < 0) ok = false;
    }
    if (!ok) {
        int n = out_size > 0 ? out_size : 1;
        zero_out<<<(n + 255)/256, 256>>>((float*)d_out, n);
        return;
    }
    bool real_first = (idx_by_sz[0][0] < idx_by_sz[2][0]);
    const float* xr = ptr_by_sz[0][real_first ? 0 : 1];
    const float* xi = ptr_by_sz[0][real_first ? 1 : 0];
    const float* mr = ptr_by_sz[1][real_first ? 0 : 1];
    const float* mi = ptr_by_sz[1][real_first ? 1 : 0];
    const float* kr = ptr_by_sz[2][real_first ? 0 : 1];
    const float* ki = ptr_by_sz[2][real_first ? 1 : 0];

    // z: [0,25) = K-transpose tiles; [25,40) = 3840 row-FFT blocks (15*256).
    p01_ktrans_rowfft<<<dim3(16, 16, NA*NA + 15), 256>>>(kr, ki, xr, xi, mr, mi);
    p2_colfft <<<dim3(GW2/4, NA, NC), 256>>>();
    p3_contract<<<FREQ/256, 256>>>();
    p4_colifft<<<dim3(GW2/8, NA, NC), 512>>>();
    p5_combine<<<dim3(NA, NH), 256>>>(mr, mi, (float*)d_out, out_size);
}

// round 16
// speedup vs baseline: 1.1888x; 1.0533x over previous
#include <cuda_runtime.h>
#include <cuda_fp16.h>

#define NH 256
#define NW 256
#define GH2 512
#define GW2 512
#define NA 5
#define NC 12
#define FREQ (GH2*GW2)   // 262144

#define SZ_X   (NA*NH*NW)      // 327680
#define SZ_MPS (NC*NH*NW)      // 786432
#define SZ_K   (NA*NA*FREQ)    // 6553600

// Skewed smem index: conflict-free for the radix-8 pass patterns.
#define IDX(i) ((i) + ((i) >> 5) + 8*((i) >> 6))
#define SMEM_N  588   // slot stride ≡ 12 (mod 32): p4 merged-read conflict-free
#define SMEM_N1 584   // slot stride ≡  8 (mod 32): p01 merged-read conflict-free

// Layouts:
//  g_fullh: [c][b or a][w(512)][h(512)] half2  (h contiguous)
//  g_mid  : [c][b][col(512)][row(256)] float2  (p01 -> p2)
//  g_mid2h: [c][a][row(256)][col(512)] half2   (p4 -> p5)
//  g_KTh  : [q=a*5+b][w][h] half2 (UNscaled; SCALE applied in p3 store)
__device__ __half2 g_fullh[NC*NA*FREQ];    // 62.9 MB
__device__ float2  g_mid  [NC*NA*NH*GW2];  // 62.9 MB
__device__ __half2 g_mid2h[NC*NA*NH*GW2];  // 31.5 MB
__device__ __half2 g_KTh  [NA*NA*FREQ];    // 26.2 MB

__device__ __forceinline__ float2 cadd(float2 a, float2 b) { return make_float2(a.x+b.x, a.y+b.y); }
__device__ __forceinline__ float2 csub(float2 a, float2 b) { return make_float2(a.x-b.x, a.y-b.y); }
__device__ __forceinline__ float2 cmul(float2 a, float2 b) {
    return make_float2(a.x*b.x - a.y*b.y, a.x*b.y + a.y*b.x);
}

// Named barrier over a 64-thread (2-warp) FFT group (p4 only). id = group+1.
__device__ __forceinline__ void bar64(int id) {
    asm volatile("bar.sync %0, 64;" :: "r"(id) : "memory");
}

__device__ __forceinline__ void build_tw(float2* tw, int t) {
    #pragma unroll
    for (int u = 0; u < 2; u++) {
        int j = t + 256*u;
        float sv, cv;
        sincosf(-6.283185307179586f * (float)j * (1.0f/512.0f), &sv, &cv);
        tw[j] = make_float2(cv, sv);
    }
}

// In-register DFT-8 (DIF), natural-order outputs.
template<bool INV>
__device__ __forceinline__ void dft8(float2* x) {
    const float H = 0.70710678118654752f;
    float2 t0 = cadd(x[0], x[4]), t4 = csub(x[0], x[4]);
    float2 t1 = cadd(x[1], x[5]), t5 = csub(x[1], x[5]);
    float2 t2 = cadd(x[2], x[6]), t6 = csub(x[2], x[6]);
    float2 t3 = cadd(x[3], x[7]), t7 = csub(x[3], x[7]);
    if (!INV) {
        t5 = make_float2(H*(t5.x + t5.y), H*(t5.y - t5.x));
        t6 = make_float2(t6.y, -t6.x);
        t7 = make_float2(H*(t7.y - t7.x), -H*(t7.x + t7.y));
    } else {
        t5 = make_float2(H*(t5.x - t5.y), H*(t5.x + t5.y));
        t6 = make_float2(-t6.y, t6.x);
        t7 = make_float2(-H*(t7.x + t7.y), H*(t7.x - t7.y));
    }
    float2 u0 = cadd(t0, t2), u2 = csub(t0, t2);
    float2 u1 = cadd(t1, t3), u3 = csub(t1, t3);
    u3 = INV ? make_float2(-u3.y, u3.x) : make_float2(u3.y, -u3.x);
    float2 v0 = cadd(t4, t6), v2 = csub(t4, t6);
    float2 v1 = cadd(t5, t7), v3 = csub(t5, t7);
    v3 = INV ? make_float2(-v3.y, v3.x) : make_float2(v3.y, -v3.x);
    x[0] = cadd(u0, u1); x[4] = csub(u0, u1);
    x[2] = cadd(u2, u3); x[6] = csub(u2, u3);
    x[1] = cadd(v0, v1); x[5] = csub(v0, v1);
    x[3] = cadd(v2, v3); x[7] = csub(v2, v3);
}

// Passes 0+1 of the 512-pt radix-8 Stockham; leaves pass-1 results (twiddled)
// in smem. Caller then block-syncs and runs the merged pass-2 (dft8 on
// s[slot][tl2+64j]) wherever the transposed output mapping wants it.
template<bool INV, bool GBAR>
__device__ __forceinline__ void fft512_2p(float2* x, float* re, float* im,
                                          const float2* tw, int tl, int bid) {
    dft8<INV>(x);
    #pragma unroll
    for (int r = 0; r < 8; r++) {
        float2 v = x[r];
        if (r > 0) {
            float2 w = tw[tl*r];
            float wy = INV ? -w.y : w.y;
            v = make_float2(x[r].x*w.x - x[r].y*wy, x[r].x*wy + x[r].y*w.x);
        }
        int o = 8*tl + r;
        re[IDX(o)] = v.x; im[IDX(o)] = v.y;
    }
    if (GBAR) bar64(bid); else __syncthreads();
    #pragma unroll
    for (int j = 0; j < 8; j++) {
        int i = tl + 64*j;
        x[j] = make_float2(re[IDX(i)], im[IDX(i)]);
    }
    if (GBAR) bar64(bid); else __syncthreads();
    dft8<INV>(x);
    {
        int q = tl & 7, p = tl >> 3;
        int ob = q + 64*p;
        #pragma unroll
        for (int r = 0; r < 8; r++) {
            float2 v = x[r];
            if (r > 0) {
                float2 w = tw[(p*r) << 3];
                float wy = INV ? -w.y : w.y;
                v = make_float2(x[r].x*w.x - x[r].y*wy, x[r].x*wy + x[r].y*w.x);
            }
            int o = ob + 8*r;
            re[IDX(o)] = v.x; im[IDX(o)] = v.y;
        }
    }
}

// Full 3-pass FFT with register return (p2/p5). Block-wide syncs (R13 form).
template<bool INV>
__device__ __forceinline__ void fft512_reg(float2* x, float* re, float* im,
                                           const float2* tw, int tl) {
    fft512_2p<INV, false>(x, re, im, tw, tl, 0);
    __syncthreads();
    #pragma unroll
    for (int j = 0; j < 8; j++) {
        int i = tl + 64*j;
        x[j] = make_float2(re[IDX(i)], im[IDX(i)]);
    }
    dft8<INV>(x);
}

__global__ void zero_out(float* __restrict__ o, int n) {
    int i = blockIdx.x*256 + threadIdx.x;
    if (i < n) o[i] = 0.f;
}

// -------- P01: grid-fused K-transpose (z<25) + row-FFT (z>=25) --------------
// Row-FFT: passes 0+1 in own slot, merged pass-2 on transposed mapping,
// direct global store (no staging round).
__global__ void __launch_bounds__(256)
p01_ktrans_rowfft(const float* __restrict__ kr, const float* __restrict__ ki,
                  const float* __restrict__ xr, const float* __restrict__ xi,
                  const float* __restrict__ mr, const float* __restrict__ mi) {
    __shared__ float tre[32][33], tim[32][33];
    __shared__ float sre[4][SMEM_N1], sim[4][SMEM_N1];
    __shared__ float2 tw[512];
    int t = threadIdx.x;
    int z = blockIdx.z;
    if (z < NA*NA) {
        // ---- K transpose tile ----
        int q = z;
        int w0 = blockIdx.x*32, h0 = blockIdx.y*32;
        int tx = t & 31, ty = t >> 5;
        size_t base = (size_t)q*FREQ;
        #pragma unroll
        for (int dy = 0; dy < 4; dy++) {
            int h = h0 + ty + 8*dy;
            size_t o = base + (size_t)h*GW2 + w0 + tx;
            tre[ty + 8*dy][tx] = kr[o];
            tim[ty + 8*dy][tx] = ki[o];
        }
        __syncthreads();
        #pragma unroll
        for (int dy = 0; dy < 4; dy++) {
            int w = w0 + ty + 8*dy;
            g_KTh[base + (size_t)w*GH2 + h0 + tx] =
                __floats2half2_rn(tre[tx][ty + 8*dy], tim[tx][ty + 8*dy]);
        }
        return;
    }
    // ---- row-FFT block ----
    build_tw(tw, t);
    int id = (z - NA*NA)*256 + blockIdx.y*16 + blockIdx.x;   // [0, 3840)
    int c  = id % NC;
    int rem = id / NC;
    int b  = rem % NA;
    int rt = rem / NA;                   // row tile [0,64)
    int f = t >> 6, tl = t & 63;
    int row = rt*4 + f;
    float2 x[8];
    #pragma unroll
    for (int j = 0; j < 8; j++) {
        int i = tl + 64*j;
        float2 v = make_float2(0.f, 0.f);
        if (j >= 2 && j < 6) {
            int col = i - 128;
            int xo = (b*NH + row)*NW + col;
            int mo = (c*NH + row)*NW + col;
            v = cmul(make_float2(xr[xo], xi[xo]), make_float2(mr[mo], mi[mo]));
        }
        x[j] = v;
    }
    __syncthreads();                       // tw table ready
    fft512_2p<false, false>(x, sre[f], sim[f], tw, tl, 0);
    __syncthreads();                       // pass-1 data visible block-wide
    // merged pass 2 on transposed mapping: thread (f2, tl2) finishes slot f2
    int f2 = t & 3, tl2 = t >> 2;
    float2 y[8];
    #pragma unroll
    for (int j = 0; j < 8; j++) {
        int i = tl2 + 64*j;
        y[j] = make_float2(sre[f2][IDX(i)], sim[f2][IDX(i)]);
    }
    dft8<false>(y);
    float2* dst = g_mid + (size_t)(c*NA + b)*GW2*NH;   // [col][row]
    int rowbase = rt*4 + f2;
    #pragma unroll
    for (int r = 0; r < 8; r++) {
        int col = tl2 + 64*r;
        dst[(size_t)col*NH + rowbase] = y[r];
    }
}

// -------- P2: 4 cols/block: col-FFT, direct reg IO (g_mid -> g_fullh) -------
__global__ void __launch_bounds__(256)
p2_colfft() {
    __shared__ float sre[4][SMEM_N], sim[4][SMEM_N];
    __shared__ float2 tw[512];
    int t = threadIdx.x;
    build_tw(tw, t);
    int f = t >> 6, tl = t & 63;
    int w = blockIdx.x*4 + f, b = blockIdx.y, c = blockIdx.z;
    const float2* src = g_mid + ((size_t)(c*NA + b)*GW2 + w)*NH;  // [col][row]
    float2 x[8];
    #pragma unroll
    for (int j = 0; j < 8; j++) {
        int i = tl + 64*j;
        x[j] = (j >= 2 && j < 6) ? src[i - 128] : make_float2(0.f, 0.f);
    }
    __syncthreads();
    fft512_reg<false>(x, sre[f], sim[f], tw, tl);
    __half2* dst = g_fullh + ((size_t)(c*NA + b)*GW2 + w)*GH2;    // [w][h]
    #pragma unroll
    for (int r = 0; r < 8; r++)
        dst[tl + 64*r] = __floats2half2_rn(x[r].x, x[r].y);
}

// -------- P3: per-frequency [A,A] contraction, all-half2 streams ------------
__global__ void __launch_bounds__(256, 4)
p3_contract() {
    int idx = blockIdx.x*256 + threadIdx.x;
    const float SCALE = 1.0f / 65536.0f;     // OS^2 / (512*512) ortho norms
    __half2 K[NA*NA];
    #pragma unroll
    for (int q = 0; q < NA*NA; q++)
        K[q] = g_KTh[(size_t)q*FREQ + idx];
    float2 fx[NA];
    #pragma unroll
    for (int b = 0; b < NA; b++)
        fx[b] = __half22float2(g_fullh[(size_t)b*FREQ + idx]);
    for (int c = 0; c < NC; c++) {
        float2 fxn[NA];
        if (c + 1 < NC) {
            #pragma unroll
            for (int b = 0; b < NA; b++)
                fxn[b] = __half22float2(g_fullh[(size_t)((c+1)*NA + b)*FREQ + idx]);
        }
        #pragma unroll
        for (int a = 0; a < NA; a++) {
            float2 acc = make_float2(0.f, 0.f);
            #pragma unroll
            for (int b = 0; b < NA; b++) {
                float2 kv = __half22float2(K[a*NA + b]);
                float2 f  = fx[b];
                acc.x += f.x*kv.x - f.y*kv.y;
                acc.y += f.x*kv.y + f.y*kv.x;
            }
            g_fullh[(size_t)(c*NA + a)*FREQ + idx] =
                __floats2half2_rn(acc.x*SCALE, acc.y*SCALE);
        }
        if (c + 1 < NC) {
            #pragma unroll
            for (int b = 0; b < NA; b++)
                fx[b] = fxn[b];
        }
    }
}

// -------- P4: 8 w/block (512 thr): col-IFFT, merged pass-2, half2 out -------
__global__ void __launch_bounds__(512)
p4_colifft() {
    __shared__ float sre[8][SMEM_N], sim[8][SMEM_N];
    __shared__ float2 tw[512];
    int t = threadIdx.x;
    if (t < 256) build_tw(tw, t);
    int f = t >> 6, tl = t & 63;
    int w0 = blockIdx.x*8;
    int w = w0 + f, a = blockIdx.y, c = blockIdx.z;
    const __half2* src = g_fullh + ((size_t)(c*NA + a)*GW2 + w)*GH2;  // [w][h]
    float2 x[8];
    #pragma unroll
    for (int j = 0; j < 8; j++)
        x[j] = __half22float2(src[tl + 64*j]);
    __syncthreads();                       // tw table ready
    fft512_2p<true, true>(x, sre[f], sim[f], tw, tl, f + 1);
    __syncthreads();                       // pass-1 data visible block-wide
    // merged pass 2 on transposed mapping: thread (f2, tl2) finishes slot f2
    int f2 = t & 7, tl2 = t >> 3;
    float2 y[8];
    #pragma unroll
    for (int j = 0; j < 8; j++) {
        int i = tl2 + 64*j;
        y[j] = make_float2(sre[f2][IDX(i)], sim[f2][IDX(i)]);
    }
    dft8<true>(y);
    __half2* dst = g_mid2h + (size_t)(c*NA + a)*NH*GW2;   // [row][col]
    int wb = w0 + f2;
    #pragma unroll
    for (int r = 2; r < 6; r++) {          // keep rows 128..383
        int h = tl2 + 64*r;
        dst[(size_t)(h - 128)*GW2 + wb] = __floats2half2_rn(y[r].x, y[r].y);
    }
}

// -------- P5: 4 coils x3 iters: row-IFFT, crop, conj(mps), sum_c ------------
// Grid: (a fastest, row) so the 5 a-blocks of one row share mps in L2.
__global__ void __launch_bounds__(256)
p5_combine(const float* __restrict__ mr, const float* __restrict__ mi,
           float* __restrict__ out, int out_cap) {
    __shared__ float sre[4][SMEM_N], sim[4][SMEM_N];
    __shared__ float2 tw[512];
    __shared__ float2 sacc[4][256];
    int t = threadIdx.x;
    build_tw(tw, t);
    int f = t >> 6, tl = t & 63;
    int a = blockIdx.x, r = blockIdx.y;
    float2 acc[4] = {{0,0},{0,0},{0,0},{0,0}};
    for (int it = 0; it < 3; it++) {
        int c = it*4 + f;
        const __half2* src = g_mid2h + ((size_t)(c*NA + a)*NH + r)*GW2;  // [row][col]
        float2 x[8];
        #pragma unroll
        for (int j = 0; j < 8; j++)
            x[j] = __half22float2(src[tl + 64*j]);
        __syncthreads();               // smem (tw at it=0; prior pass reads after)
        fft512_reg<true>(x, sre[f], sim[f], tw, tl);
        #pragma unroll
        for (int rr = 2; rr < 6; rr++) {
            int col = tl + 64*rr - 128;
            int mo = (c*NH + r)*NW + col;
            float2 m = make_float2(mr[mo], -mi[mo]);
            acc[rr-2] = cadd(acc[rr-2], cmul(x[rr], m));
        }
    }
    #pragma unroll
    for (int jj = 0; jj < 4; jj++)
        sacc[f][tl + 64*jj] = acc[jj];
    __syncthreads();
    int col = t;
    float2 s = cadd(cadd(sacc[0][col], sacc[1][col]),
                    cadd(sacc[2][col], sacc[3][col]));
    int i = (a*NH + r)*NW + col;
    if (i        < out_cap) out[i]        = s.x;   // real plane
    if (i + SZ_X < out_cap) out[i + SZ_X] = s.y;   // imag plane
}

extern "C" void kernel_launch(void* const* d_in, const int* in_sizes, int n_in,
                              void* d_out, int out_size) {
    // ---- strict binding by verified size fingerprint (validated in R5) ----
    const float *ptr_by_sz[3][2] = {{0,0},{0,0},{0,0}};
    int idx_by_sz[3][2] = {{-1,-1},{-1,-1},{-1,-1}};
    bool ok = (n_in == 6);
    if (ok) {
        for (int i = 0; i < 6; i++) {
            long long s = in_sizes[i];
            int which = -1;
            if (s == SZ_X   || s == (long long)SZ_X*4)   which = 0;
            else if (s == SZ_MPS || s == (long long)SZ_MPS*4) which = 1;
            else if (s == SZ_K   || s == (long long)SZ_K*4)   which = 2;
            if (which < 0) { ok = false; break; }
            if      (idx_by_sz[which][0] < 0) { idx_by_sz[which][0] = i; ptr_by_sz[which][0] = (const float*)d_in[i]; }
            else if (idx_by_sz[which][1] < 0) { idx_by_sz[which][1] = i; ptr_by_sz[which][1] = (const float*)d_in[i]; }
            else { ok = false; break; }
        }
        if (ok)
            for (int w = 0; w < 3; w++)
                if (idx_by_sz[w][1] < 0) ok = false;
    }
    if (!ok) {
        int n = out_size > 0 ? out_size : 1;
        zero_out<<<(n + 255)/256, 256>>>((float*)d_out, n);
        return;
    }
    bool real_first = (idx_by_sz[0][0] < idx_by_sz[2][0]);
    const float* xr = ptr_by_sz[0][real_first ? 0 : 1];
    const float* xi = ptr_by_sz[0][real_first ? 1 : 0];
    const float* mr = ptr_by_sz[1][real_first ? 0 : 1];
    const float* mi = ptr_by_sz[1][real_first ? 1 : 0];
    const float* kr = ptr_by_sz[2][real_first ? 0 : 1];
    const float* ki = ptr_by_sz[2][real_first ? 1 : 0];

    // z: [0,25) = K-transpose tiles; [25,40) = 3840 row-FFT blocks (15*256).
    p01_ktrans_rowfft<<<dim3(16, 16, NA*NA + 15), 256>>>(kr, ki, xr, xi, mr, mi);
    p2_colfft <<<dim3(GW2/4, NA, NC), 256>>>();
    p3_contract<<<FREQ/256, 256>>>();
    p4_colifft<<<dim3(GW2/8, NA, NC), 512>>>();
    p5_combine<<<dim3(NA, NH), 256>>>(mr, mi, (float*)d_out, out_size);
}